// round 3
// baseline (speedup 1.0000x reference)
#include <cuda_runtime.h>
#include <cstdint>
#include <math.h>

#define MAXN 100000
#define MAXE 1600000
#define D 64
#define EPSF 1e-12f
#define SEPS 1e-6f
#define TAUF 0.5f

// ---- scratch (device globals: no allocation allowed) ----
__device__ float    g_deg[MAXN];
__device__ float    g_invd2[MAXN];     // 2 / max(deg, eps)
__device__ float    g_rowsum[MAXN];
__device__ float    g_cnt[MAXN];
__device__ float    g_ksum[MAXN];
__device__ float    g_rho[MAXN];
__device__ float    g_irs[MAXN];       // 1 / max(rowsum, eps)
__device__ float    g_kappa[MAXE];
__device__ float    g_whalf[MAXE];
__device__ __align__(16) float g_agg[MAXN * D];   // sum_e w_norm * x[col]
__device__ unsigned g_maxbits;
__device__ float    g_dt;
__device__ int      g_is64;

// index fetch that works for both int32 and int64 edge_index buffers
__device__ __forceinline__ int get_idx(const void* ei, long long pos) {
    if (g_is64) return (int)((const long long*)ei)[pos];
    return ((const int*)ei)[pos];
}

// ---- detect: int64 buffers have all-zero high words (indices < 2^31) ----
__global__ void k_detect(const int* __restrict__ eib) {
    __shared__ int any;
    if (threadIdx.x == 0) any = 0;
    __syncthreads();
    int acc = 0;
    // inspect 2048 candidate high-words (word indices 1,3,5,...)
    for (int j = threadIdx.x; j < 2048; j += blockDim.x)
        acc |= eib[2 * j + 1];
    if (acc != 0) atomicOr(&any, 1);
    __syncthreads();
    if (threadIdx.x == 0) g_is64 = (any == 0) ? 1 : 0;
}

// ---- 0: zero scratch ----
__global__ void k_zero(int n_nodes) {
    int i = blockIdx.x * blockDim.x + threadIdx.x;
    int tot = n_nodes * D;
    if (i < tot) g_agg[i] = 0.f;
    if (i < n_nodes) {
        g_deg[i] = 0.f; g_rowsum[i] = 0.f; g_cnt[i] = 0.f; g_ksum[i] = 0.f;
    }
    if (i == 0) g_maxbits = 0u;
}

// ---- 1: weighted out-degree ----
__global__ void k_deg(const void* __restrict__ ei,
                      const float* __restrict__ w, int n_edges) {
    int e = blockIdx.x * blockDim.x + threadIdx.x;
    if (e >= n_edges) return;
    int r = get_idx(ei, e);
    atomicAdd(&g_deg[r], w[e]);
}

// ---- 1b: per-node 2/deg ----
__global__ void k_invd(int n_nodes) {
    int n = blockIdx.x * blockDim.x + threadIdx.x;
    if (n >= n_nodes) return;
    g_invd2[n] = 2.f / fmaxf(g_deg[n], EPSF);
}

// ---- 2: kappa per edge + global max|kappa| ----
__global__ void k_kappa(const void* __restrict__ ei, int n_edges) {
    int e = blockIdx.x * blockDim.x + threadIdx.x;
    float m = 0.f;
    if (e < n_edges) {
        int r = get_idx(ei, e);
        int c = get_idx(ei, (long long)n_edges + e);
        float kap = g_invd2[r] + g_invd2[c] - 2.f;
        g_kappa[e] = kap;
        m = fabsf(kap);
    }
    #pragma unroll
    for (int o = 16; o > 0; o >>= 1)
        m = fmaxf(m, __shfl_xor_sync(0xffffffffu, m, o));
    if ((threadIdx.x & 31) == 0)
        atomicMax(&g_maxbits, __float_as_uint(m));   // values >= 0: uint order == float order
}

// ---- 2b: CFL step ----
__global__ void k_dt() {
    g_dt = 0.5f / (__uint_as_float(g_maxbits) + 1e-6f);
}

// ---- 3: half-step + surgery mask + row accumulators ----
__global__ void k_whalf(const void* __restrict__ ei,
                        const float* __restrict__ w, int n_edges) {
    int e = blockIdx.x * blockDim.x + threadIdx.x;
    if (e >= n_edges) return;
    float kap = g_kappa[e];
    float wh = fmaxf(w[e] * (1.f - 0.5f * g_dt * kap), 0.f);
    bool mask = wh > SEPS;
    if (!mask) wh = 0.f;
    g_whalf[e] = wh;
    int r = get_idx(ei, e);
    atomicAdd(&g_rowsum[r], wh);
    if (mask) {
        atomicAdd(&g_cnt[r], 1.f);
        atomicAdd(&g_ksum[r], kap);
    }
}

// ---- 4: per-node inverse rowsum + curvature gate ----
__global__ void k_node(int n_nodes) {
    int n = blockIdx.x * blockDim.x + threadIdx.x;
    if (n >= n_nodes) return;
    g_irs[n] = 1.f / fmaxf(g_rowsum[n], EPSF);
    float mk = g_ksum[n] / fmaxf(g_cnt[n], 1.f);
    g_rho[n] = 1.f / (1.f + expf(-mk));
}

// ---- 5: x-space scatter (16 lanes per edge, vector red) ----
__global__ void k_scatter(const float* __restrict__ x,
                          const void* __restrict__ ei,
                          float* __restrict__ out_wn, int n_edges) {
    long long gt = (long long)blockIdx.x * blockDim.x + threadIdx.x;
    int e   = (int)(gt >> 4);
    int sub = (int)(gt & 15);
    if (e >= n_edges) return;
    int r = get_idx(ei, e);
    float wn = g_whalf[e] * g_irs[r];
    if (out_wn != nullptr && sub == 0) out_wn[e] = wn;
    if (wn != 0.f) {
        int c = get_idx(ei, (long long)n_edges + e);
        float4 v = ((const float4*)(x + (size_t)c * D))[sub];
        v.x *= wn; v.y *= wn; v.z *= wn; v.w *= wn;
        float* dst = g_agg + (size_t)r * D + sub * 4;
        asm volatile("red.global.add.v4.f32 [%0], {%1,%2,%3,%4};"
                     :: "l"(dst), "f"(v.x), "f"(v.y), "f"(v.z), "f"(v.w)
                     : "memory");
    }
}

// ---- 6: fused dual GEMM: out = (rho*x)@Ws^T + agg@Wn^T + tau*x ----
#define TILE_N 128
__global__ __launch_bounds__(128) void k_gemm(const float* __restrict__ x,
                                              const float* __restrict__ Ws,
                                              const float* __restrict__ Wn,
                                              float* __restrict__ out,
                                              int n_nodes) {
    extern __shared__ float smem[];
    float* sxT = smem;                 // [64][128]  rho*x transposed
    float* saT = sxT + D * TILE_N;     // [64][128]  agg transposed
    float* swT = saT + D * TILE_N;     // [64][64]   Ws[k][d]
    float* snT = swT + D * D;          // [64][64]   Wn[k][d]

    int t = threadIdx.x;
    int nbase = blockIdx.x * TILE_N;

    for (int i = t; i < D * D; i += 128) {
        int k = i >> 6, d = i & 63;
        swT[k * D + d] = Ws[d * D + k];
        snT[k * D + d] = Wn[d * D + k];
    }
    for (int i = t; i < TILE_N * (D / 4); i += 128) {
        int n  = i & (TILE_N - 1);
        int k4 = i >> 7;                 // 0..15
        int gn = nbase + n;
        float4 xv = make_float4(0.f, 0.f, 0.f, 0.f);
        float4 av = make_float4(0.f, 0.f, 0.f, 0.f);
        float rho = 0.f;
        if (gn < n_nodes) {
            xv  = *(const float4*)(x     + (size_t)gn * D + k4 * 4);
            av  = *(const float4*)(g_agg + (size_t)gn * D + k4 * 4);
            rho = g_rho[gn];
        }
        sxT[(k4 * 4 + 0) * TILE_N + n] = rho * xv.x;
        sxT[(k4 * 4 + 1) * TILE_N + n] = rho * xv.y;
        sxT[(k4 * 4 + 2) * TILE_N + n] = rho * xv.z;
        sxT[(k4 * 4 + 3) * TILE_N + n] = rho * xv.w;
        saT[(k4 * 4 + 0) * TILE_N + n] = av.x;
        saT[(k4 * 4 + 1) * TILE_N + n] = av.y;
        saT[(k4 * 4 + 2) * TILE_N + n] = av.z;
        saT[(k4 * 4 + 3) * TILE_N + n] = av.w;
    }
    __syncthreads();

    int ng = t >> 3;   // 0..15 -> nodes ng*8 .. +7
    int dg = t & 7;    // 0..7  -> dims  dg*8 .. +7

    float acc[8][8];
    #pragma unroll
    for (int i = 0; i < 8; i++)
        #pragma unroll
        for (int j = 0; j < 8; j++) acc[i][j] = 0.f;

    #pragma unroll 4
    for (int k = 0; k < D; k++) {
        float4 a0 = *(float4*)&sxT[k * TILE_N + ng * 8];
        float4 a1 = *(float4*)&sxT[k * TILE_N + ng * 8 + 4];
        float4 g0 = *(float4*)&saT[k * TILE_N + ng * 8];
        float4 g1 = *(float4*)&saT[k * TILE_N + ng * 8 + 4];
        float4 b0 = *(float4*)&swT[k * D + dg * 8];
        float4 b1 = *(float4*)&swT[k * D + dg * 8 + 4];
        float4 c0 = *(float4*)&snT[k * D + dg * 8];
        float4 c1 = *(float4*)&snT[k * D + dg * 8 + 4];
        float av[8] = {a0.x, a0.y, a0.z, a0.w, a1.x, a1.y, a1.z, a1.w};
        float gv[8] = {g0.x, g0.y, g0.z, g0.w, g1.x, g1.y, g1.z, g1.w};
        float bv[8] = {b0.x, b0.y, b0.z, b0.w, b1.x, b1.y, b1.z, b1.w};
        float cv[8] = {c0.x, c0.y, c0.z, c0.w, c1.x, c1.y, c1.z, c1.w};
        #pragma unroll
        for (int i = 0; i < 8; i++)
            #pragma unroll
            for (int j = 0; j < 8; j++)
                acc[i][j] += av[i] * bv[j] + gv[i] * cv[j];
    }

    #pragma unroll
    for (int i = 0; i < 8; i++) {
        int gn = nbase + ng * 8 + i;
        if (gn >= n_nodes) continue;
        const float* xr = x + (size_t)gn * D + dg * 8;
        float* orow = out + (size_t)gn * D + dg * 8;
        float4 x0 = *(const float4*)(xr);
        float4 x1 = *(const float4*)(xr + 4);
        float4 o0 = make_float4(acc[i][0] + TAUF * x0.x, acc[i][1] + TAUF * x0.y,
                                acc[i][2] + TAUF * x0.z, acc[i][3] + TAUF * x0.w);
        float4 o1 = make_float4(acc[i][4] + TAUF * x1.x, acc[i][5] + TAUF * x1.y,
                                acc[i][6] + TAUF * x1.z, acc[i][7] + TAUF * x1.w);
        *(float4*)(orow)     = o0;
        *(float4*)(orow + 4) = o1;
    }
}

// ---- 7: edge_index -> float copy into output region ----
__global__ void k_eicopy(const void* __restrict__ ei, float* __restrict__ o, int n2e) {
    int i = blockIdx.x * blockDim.x + threadIdx.x;
    if (i < n2e) o[i] = (float)get_idx(ei, i);
}

extern "C" void kernel_launch(void* const* d_in, const int* in_sizes, int n_in,
                              void* d_out, int out_size) {
    const float* x  = (const float*)d_in[0];
    const void*  ei = d_in[1];
    const float* w  = (const float*)d_in[2];
    const float* Ws = (const float*)d_in[3];
    const float* Wn = (const float*)d_in[4];

    int n_nodes = in_sizes[0] / D;
    int n_edges = in_sizes[1] / 2;

    float* out_main = (float*)d_out;
    float* out_ei = nullptr;
    float* out_wn = nullptr;
    long long need_full = (long long)n_nodes * D + 3LL * n_edges;
    bool full = ((long long)out_size >= need_full);
    if (full) {
        out_ei = out_main + (size_t)n_nodes * D;
        out_wn = out_ei + (size_t)2 * n_edges;
    }

    const int T = 256;
    int tot = n_nodes * D;

    k_detect<<<1, 256>>>((const int*)ei);
    k_zero<<<(tot + T - 1) / T, T>>>(n_nodes);
    k_deg<<<(n_edges + T - 1) / T, T>>>(ei, w, n_edges);
    k_invd<<<(n_nodes + T - 1) / T, T>>>(n_nodes);
    k_kappa<<<(n_edges + T - 1) / T, T>>>(ei, n_edges);
    k_dt<<<1, 1>>>();
    k_whalf<<<(n_edges + T - 1) / T, T>>>(ei, w, n_edges);
    k_node<<<(n_nodes + T - 1) / T, T>>>(n_nodes);

    long long sc_threads = (long long)n_edges * 16;
    int sc_blocks = (int)((sc_threads + T - 1) / T);
    k_scatter<<<sc_blocks, T>>>(x, ei, out_wn, n_edges);

    int smem_bytes = (D * TILE_N * 2 + D * D * 2) * (int)sizeof(float); // 96KB
    cudaFuncSetAttribute(k_gemm, cudaFuncAttributeMaxDynamicSharedMemorySize, smem_bytes);
    int gblocks = (n_nodes + TILE_N - 1) / TILE_N;
    k_gemm<<<gblocks, 128, smem_bytes>>>(x, Ws, Wn, out_main, n_nodes);

    if (full) {
        int n2e = 2 * n_edges;
        k_eicopy<<<(n2e + T - 1) / T, T>>>(ei, out_ei, n2e);
    }
}

// round 4
// speedup vs baseline: 1.1344x; 1.1344x over previous
#include <cuda_runtime.h>
#include <cstdint>
#include <math.h>

#define MAXN 100000
#define MAXE 1600000
#define D 64
#define EPSF 1e-12f
#define SEPS 1e-6f
#define TAUF 0.5f

// ---- scratch (device globals: no allocation allowed) ----
__device__ float    g_deg[MAXN];
__device__ float    g_invd2[MAXN];     // 2 / max(deg, eps)
__device__ float    g_rowsum[MAXN];
__device__ float    g_cnt[MAXN];
__device__ float    g_ksum[MAXN];
__device__ float    g_rho[MAXN];
__device__ float    g_irs[MAXN];       // 1 / max(rowsum, eps)
__device__ int      g_row[MAXE];
__device__ int      g_col[MAXE];
__device__ float    g_kappa[MAXE];
__device__ float    g_whalf[MAXE];
__device__ __align__(16) float g_agg[MAXN * D];   // sum_e w_norm * x[col]
__device__ unsigned g_maxbits;
__device__ float    g_dt;
__device__ int      g_is64;

__device__ __forceinline__ int get_idx(const void* ei, long long pos) {
    if (g_is64) return (int)((const long long*)ei)[pos];
    return ((const int*)ei)[pos];
}

// ---- detect: int64 buffers have all-zero high words (indices < 2^31) ----
__global__ void k_detect(const int* __restrict__ eib) {
    __shared__ int any;
    if (threadIdx.x == 0) any = 0;
    __syncthreads();
    int acc = 0;
    for (int j = threadIdx.x; j < 2048; j += blockDim.x)
        acc |= eib[2 * j + 1];
    if (acc != 0) atomicOr(&any, 1);
    __syncthreads();
    if (threadIdx.x == 0) g_is64 = (any == 0) ? 1 : 0;
}

// ---- 0: zero scratch ----
__global__ void k_zero(int n_nodes) {
    int i = blockIdx.x * blockDim.x + threadIdx.x;
    int tot = n_nodes * D;
    if (i < tot) g_agg[i] = 0.f;
    if (i < n_nodes) {
        g_deg[i] = 0.f; g_rowsum[i] = 0.f; g_cnt[i] = 0.f; g_ksum[i] = 0.f;
    }
    if (i == 0) g_maxbits = 0u;
}

// ---- 1: convert indices to int32 + write edge_index output + weighted degree ----
__global__ void k_cvtdeg(const void* __restrict__ ei, const float* __restrict__ w,
                         float* __restrict__ out_ei, int n_edges) {
    int e = blockIdx.x * blockDim.x + threadIdx.x;
    if (e >= n_edges) return;
    int r = get_idx(ei, e);
    int c = get_idx(ei, (long long)n_edges + e);
    g_row[e] = r;
    g_col[e] = c;
    if (out_ei) {
        out_ei[e] = (float)r;
        out_ei[n_edges + e] = (float)c;
    }
    atomicAdd(&g_deg[r], w[e]);
}

// ---- 1b: per-node 2/deg ----
__global__ void k_invd(int n_nodes) {
    int n = blockIdx.x * blockDim.x + threadIdx.x;
    if (n >= n_nodes) return;
    g_invd2[n] = 2.f / fmaxf(g_deg[n], EPSF);
}

// ---- 2: kappa per edge + global max|kappa| ----
__global__ void k_kappa(int n_edges) {
    int e = blockIdx.x * blockDim.x + threadIdx.x;
    float m = 0.f;
    if (e < n_edges) {
        float kap = g_invd2[g_row[e]] + g_invd2[g_col[e]] - 2.f;
        g_kappa[e] = kap;
        m = fabsf(kap);
    }
    #pragma unroll
    for (int o = 16; o > 0; o >>= 1)
        m = fmaxf(m, __shfl_xor_sync(0xffffffffu, m, o));
    if ((threadIdx.x & 31) == 0)
        atomicMax(&g_maxbits, __float_as_uint(m));
}

// ---- 2b: CFL step ----
__global__ void k_dt() {
    g_dt = 0.5f / (__uint_as_float(g_maxbits) + 1e-6f);
}

// ---- 3: half-step + surgery mask + row accumulators ----
__global__ void k_whalf(const float* __restrict__ w, int n_edges) {
    int e = blockIdx.x * blockDim.x + threadIdx.x;
    if (e >= n_edges) return;
    float kap = g_kappa[e];
    float wh = fmaxf(w[e] * (1.f - 0.5f * g_dt * kap), 0.f);
    bool mask = wh > SEPS;
    if (!mask) wh = 0.f;
    g_whalf[e] = wh;
    int r = g_row[e];
    atomicAdd(&g_rowsum[r], wh);
    if (mask) {
        atomicAdd(&g_cnt[r], 1.f);
        atomicAdd(&g_ksum[r], kap);
    }
}

// ---- 4: per-node inverse rowsum + curvature gate ----
__global__ void k_node(int n_nodes) {
    int n = blockIdx.x * blockDim.x + threadIdx.x;
    if (n >= n_nodes) return;
    g_irs[n] = 1.f / fmaxf(g_rowsum[n], EPSF);
    float mk = g_ksum[n] / fmaxf(g_cnt[n], 1.f);
    g_rho[n] = 1.f / (1.f + expf(-mk));
}

// ---- 5: x-space scatter (16 lanes per edge, vector red) ----
__global__ void k_scatter(const float* __restrict__ x,
                          float* __restrict__ out_wn, int n_edges) {
    long long gt = (long long)blockIdx.x * blockDim.x + threadIdx.x;
    int e   = (int)(gt >> 4);
    int sub = (int)(gt & 15);
    if (e >= n_edges) return;
    int r = g_row[e];
    float wn = g_whalf[e] * g_irs[r];
    if (out_wn != nullptr && sub == 0) out_wn[e] = wn;
    if (wn != 0.f) {
        int c = g_col[e];
        float4 v = ((const float4*)(x + (size_t)c * D))[sub];
        v.x *= wn; v.y *= wn; v.z *= wn; v.w *= wn;
        float* dst = g_agg + (size_t)r * D + sub * 4;
        asm volatile("red.global.add.v4.f32 [%0], {%1,%2,%3,%4};"
                     :: "l"(dst), "f"(v.x), "f"(v.y), "f"(v.z), "f"(v.w)
                     : "memory");
    }
}

// ---- FFMA2 helpers (packed f32x2, sm_103a) ----
__device__ __forceinline__ unsigned long long dup2(float v) {
    unsigned long long r;
    asm("mov.b64 %0, {%1, %1};" : "=l"(r) : "r"(__float_as_uint(v)));
    return r;
}
__device__ __forceinline__ void ffma2(unsigned long long& acc,
                                      unsigned long long a, unsigned long long b) {
    asm("fma.rn.f32x2 %0, %1, %2, %0;" : "+l"(acc) : "l"(a), "l"(b));
}
__device__ __forceinline__ void unpack2(unsigned long long v, float& lo, float& hi) {
    unsigned l, h;
    asm("mov.b64 {%0, %1}, %2;" : "=r"(l), "=r"(h) : "l"(v));
    lo = __uint_as_float(l); hi = __uint_as_float(h);
}

// ---- 6: fused dual GEMM (FFMA2): out = (rho*x)@Ws^T + agg@Wn^T + tau*x ----
#define TILE_N 128
__global__ __launch_bounds__(128, 2) void k_gemm(const float* __restrict__ x,
                                                 const float* __restrict__ Ws,
                                                 const float* __restrict__ Wn,
                                                 float* __restrict__ out,
                                                 int n_nodes) {
    extern __shared__ float smem[];
    float* sxT = smem;                 // [64][128]  rho*x transposed
    float* saT = sxT + D * TILE_N;     // [64][128]  agg transposed
    float* swT = saT + D * TILE_N;     // [64][64]   Ws[k][d]
    float* snT = swT + D * D;          // [64][64]   Wn[k][d]

    int t = threadIdx.x;
    int nbase = blockIdx.x * TILE_N;

    for (int i = t; i < D * D; i += 128) {
        int k = i >> 6, d = i & 63;
        swT[k * D + d] = Ws[d * D + k];
        snT[k * D + d] = Wn[d * D + k];
    }
    for (int i = t; i < TILE_N * (D / 4); i += 128) {
        int n  = i & (TILE_N - 1);
        int k4 = i >> 7;                 // 0..15
        int gn = nbase + n;
        float4 xv = make_float4(0.f, 0.f, 0.f, 0.f);
        float4 av = make_float4(0.f, 0.f, 0.f, 0.f);
        float rho = 0.f;
        if (gn < n_nodes) {
            xv  = *(const float4*)(x     + (size_t)gn * D + k4 * 4);
            av  = *(const float4*)(g_agg + (size_t)gn * D + k4 * 4);
            rho = g_rho[gn];
        }
        sxT[(k4 * 4 + 0) * TILE_N + n] = rho * xv.x;
        sxT[(k4 * 4 + 1) * TILE_N + n] = rho * xv.y;
        sxT[(k4 * 4 + 2) * TILE_N + n] = rho * xv.z;
        sxT[(k4 * 4 + 3) * TILE_N + n] = rho * xv.w;
        saT[(k4 * 4 + 0) * TILE_N + n] = av.x;
        saT[(k4 * 4 + 1) * TILE_N + n] = av.y;
        saT[(k4 * 4 + 2) * TILE_N + n] = av.z;
        saT[(k4 * 4 + 3) * TILE_N + n] = av.w;
    }
    __syncthreads();

    int ng = t >> 3;   // 0..15 -> nodes ng*8 .. +7
    int dg = t & 7;    // 0..7  -> dims  dg*8 .. +7 (4 packed pairs)

    unsigned long long acc[8][4];
    #pragma unroll
    for (int i = 0; i < 8; i++)
        #pragma unroll
        for (int j = 0; j < 4; j++) acc[i][j] = 0ull;

    #pragma unroll 2
    for (int k = 0; k < D; k++) {
        float4 a0 = *(float4*)&sxT[k * TILE_N + ng * 8];
        float4 a1 = *(float4*)&sxT[k * TILE_N + ng * 8 + 4];
        float4 g0 = *(float4*)&saT[k * TILE_N + ng * 8];
        float4 g1 = *(float4*)&saT[k * TILE_N + ng * 8 + 4];
        ulonglong2 b0 = *(ulonglong2*)&swT[k * D + dg * 8];
        ulonglong2 b1 = *(ulonglong2*)&swT[k * D + dg * 8 + 4];
        ulonglong2 c0 = *(ulonglong2*)&snT[k * D + dg * 8];
        ulonglong2 c1 = *(ulonglong2*)&snT[k * D + dg * 8 + 4];
        unsigned long long bv[4] = {b0.x, b0.y, b1.x, b1.y};
        unsigned long long cv[4] = {c0.x, c0.y, c1.x, c1.y};
        float av[8] = {a0.x, a0.y, a0.z, a0.w, a1.x, a1.y, a1.z, a1.w};
        float gv[8] = {g0.x, g0.y, g0.z, g0.w, g1.x, g1.y, g1.z, g1.w};
        #pragma unroll
        for (int i = 0; i < 8; i++) {
            unsigned long long ad = dup2(av[i]);
            unsigned long long gd = dup2(gv[i]);
            #pragma unroll
            for (int j = 0; j < 4; j++) {
                ffma2(acc[i][j], ad, bv[j]);
                ffma2(acc[i][j], gd, cv[j]);
            }
        }
    }

    #pragma unroll
    for (int i = 0; i < 8; i++) {
        int gn = nbase + ng * 8 + i;
        if (gn >= n_nodes) continue;
        const float* xr = x + (size_t)gn * D + dg * 8;
        float* orow = out + (size_t)gn * D + dg * 8;
        float4 x0 = *(const float4*)(xr);
        float4 x1 = *(const float4*)(xr + 4);
        float r0, r1, r2, r3, r4, r5, r6, r7;
        unpack2(acc[i][0], r0, r1);
        unpack2(acc[i][1], r2, r3);
        unpack2(acc[i][2], r4, r5);
        unpack2(acc[i][3], r6, r7);
        float4 o0 = make_float4(r0 + TAUF * x0.x, r1 + TAUF * x0.y,
                                r2 + TAUF * x0.z, r3 + TAUF * x0.w);
        float4 o1 = make_float4(r4 + TAUF * x1.x, r5 + TAUF * x1.y,
                                r6 + TAUF * x1.z, r7 + TAUF * x1.w);
        *(float4*)(orow)     = o0;
        *(float4*)(orow + 4) = o1;
    }
}

extern "C" void kernel_launch(void* const* d_in, const int* in_sizes, int n_in,
                              void* d_out, int out_size) {
    const float* x  = (const float*)d_in[0];
    const void*  ei = d_in[1];
    const float* w  = (const float*)d_in[2];
    const float* Ws = (const float*)d_in[3];
    const float* Wn = (const float*)d_in[4];

    int n_nodes = in_sizes[0] / D;
    int n_edges = in_sizes[1] / 2;

    float* out_main = (float*)d_out;
    float* out_ei = nullptr;
    float* out_wn = nullptr;
    long long need_full = (long long)n_nodes * D + 3LL * n_edges;
    bool full = ((long long)out_size >= need_full);
    if (full) {
        out_ei = out_main + (size_t)n_nodes * D;
        out_wn = out_ei + (size_t)2 * n_edges;
    }

    const int T = 256;
    int tot = n_nodes * D;

    k_detect<<<1, 256>>>((const int*)ei);
    k_zero<<<(tot + T - 1) / T, T>>>(n_nodes);
    k_cvtdeg<<<(n_edges + T - 1) / T, T>>>(ei, w, out_ei, n_edges);
    k_invd<<<(n_nodes + T - 1) / T, T>>>(n_nodes);
    k_kappa<<<(n_edges + T - 1) / T, T>>>(n_edges);
    k_dt<<<1, 1>>>();
    k_whalf<<<(n_edges + T - 1) / T, T>>>(w, n_edges);
    k_node<<<(n_nodes + T - 1) / T, T>>>(n_nodes);

    long long sc_threads = (long long)n_edges * 16;
    int sc_blocks = (int)((sc_threads + T - 1) / T);
    k_scatter<<<sc_blocks, T>>>(x, out_wn, n_edges);

    int smem_bytes = (D * TILE_N * 2 + D * D * 2) * (int)sizeof(float); // 96KB
    cudaFuncSetAttribute(k_gemm, cudaFuncAttributeMaxDynamicSharedMemorySize, smem_bytes);
    int gblocks = (n_nodes + TILE_N - 1) / TILE_N;
    k_gemm<<<gblocks, 128, smem_bytes>>>(x, Ws, Wn, out_main, n_nodes);
}

// round 5
// speedup vs baseline: 1.3271x; 1.1699x over previous
#include <cuda_runtime.h>
#include <cstdint>
#include <math.h>

#define MAXN 100000
#define MAXE 1600000
#define D 64
#define EPSF 1e-12f
#define SEPS 1e-6f
#define TAUF 0.5f

// ---- scratch (device globals: no allocation allowed) ----
__device__ float    g_deg[MAXN];
__device__ float    g_rowsum[MAXN];
__device__ float    g_cnt[MAXN];
__device__ float    g_ksum[MAXN];
__device__ float    g_rho[MAXN];
__device__ float    g_irs[MAXN];       // 1 / max(rowsum, eps)
__device__ int      g_row[MAXE];
__device__ int      g_col[MAXE];
__device__ float    g_kappa[MAXE];
__device__ float    g_whalf[MAXE];
__device__ __align__(16) float g_agg[MAXN * D];   // sum_e w_norm * x[col]
__device__ unsigned g_maxbits;
__device__ int      g_is64;

__device__ __forceinline__ int get_idx(const void* ei, long long pos) {
    if (g_is64) return (int)((const long long*)ei)[pos];
    return ((const int*)ei)[pos];
}

// ---- 0: zero scratch + dtype detect (block 0) ----
__global__ void k_init(const int* __restrict__ eib, int n_nodes) {
    if (blockIdx.x == 0) {
        __shared__ int any;
        if (threadIdx.x == 0) any = 0;
        __syncthreads();
        int acc = 0;
        for (int j = threadIdx.x; j < 2048; j += blockDim.x)
            acc |= eib[2 * j + 1];           // high words of first 2048 int64s
        if (acc != 0) atomicOr(&any, 1);
        __syncthreads();
        if (threadIdx.x == 0) {
            g_is64 = (any == 0) ? 1 : 0;
            g_maxbits = 0u;
        }
    }
    int i = blockIdx.x * blockDim.x + threadIdx.x;
    int tot = n_nodes * D;
    if (i < tot) g_agg[i] = 0.f;
    if (i < n_nodes) {
        g_deg[i] = 0.f; g_rowsum[i] = 0.f; g_cnt[i] = 0.f; g_ksum[i] = 0.f;
    }
}

// ---- 1: convert indices to int32 + write edge_index output + weighted degree ----
__global__ void k_cvtdeg(const void* __restrict__ ei, const float* __restrict__ w,
                         float* __restrict__ out_ei, int n_edges) {
    int e = blockIdx.x * blockDim.x + threadIdx.x;
    if (e >= n_edges) return;
    int r = get_idx(ei, e);
    int c = get_idx(ei, (long long)n_edges + e);
    g_row[e] = r;
    g_col[e] = c;
    if (out_ei) {
        out_ei[e] = (float)r;
        out_ei[n_edges + e] = (float)c;
    }
    atomicAdd(&g_deg[r], w[e]);
}

// ---- 2: kappa per edge (invd2 inline) + global max|kappa| ----
__global__ void k_kappa(int n_edges) {
    int e = blockIdx.x * blockDim.x + threadIdx.x;
    float m = 0.f;
    if (e < n_edges) {
        float idu = 2.f / fmaxf(g_deg[g_row[e]], EPSF);
        float idv = 2.f / fmaxf(g_deg[g_col[e]], EPSF);
        float kap = idu + idv - 2.f;
        g_kappa[e] = kap;
        m = fabsf(kap);
    }
    #pragma unroll
    for (int o = 16; o > 0; o >>= 1)
        m = fmaxf(m, __shfl_xor_sync(0xffffffffu, m, o));
    if ((threadIdx.x & 31) == 0)
        atomicMax(&g_maxbits, __float_as_uint(m));   // m >= 0: uint order == float order
}

// ---- 3: half-step (dt inline) + surgery mask + row accumulators ----
__global__ void k_whalf(const float* __restrict__ w, int n_edges) {
    int e = blockIdx.x * blockDim.x + threadIdx.x;
    if (e >= n_edges) return;
    float dt = 0.5f / (__uint_as_float(g_maxbits) + 1e-6f);
    float kap = g_kappa[e];
    float wh = fmaxf(w[e] * (1.f - 0.5f * dt * kap), 0.f);
    bool mask = wh > SEPS;
    if (!mask) wh = 0.f;
    g_whalf[e] = wh;
    int r = g_row[e];
    atomicAdd(&g_rowsum[r], wh);
    if (mask) {
        atomicAdd(&g_cnt[r], 1.f);
        atomicAdd(&g_ksum[r], kap);
    }
}

// ---- 4: per-node inverse rowsum + curvature gate ----
__global__ void k_node(int n_nodes) {
    int n = blockIdx.x * blockDim.x + threadIdx.x;
    if (n >= n_nodes) return;
    g_irs[n] = 1.f / fmaxf(g_rowsum[n], EPSF);
    float mk = g_ksum[n] / fmaxf(g_cnt[n], 1.f);
    g_rho[n] = 1.f / (1.f + expf(-mk));
}

// ---- 5: x-space scatter, warp-cooperative ----
// Each warp: loads 32 consecutive edges coalesced, writes out_wn coalesced,
// then 16 shfl-broadcast iterations scatter 2 edges at a time (16 lanes x float4).
__global__ void k_scatter(const float* __restrict__ x,
                          float* __restrict__ out_wn, int n_edges) {
    int warp_g = (blockIdx.x * blockDim.x + threadIdx.x) >> 5;
    int lane = threadIdx.x & 31;
    int sub  = lane & 15;
    int half = lane >> 4;
    int ebase = warp_g * 32;
    if (ebase >= n_edges) return;
    int e = ebase + lane;

    int r = 0, c = 0;
    float wn = 0.f;
    if (e < n_edges) {
        r = g_row[e];
        c = g_col[e];
        wn = g_whalf[e] * g_irs[r];
        if (out_wn) out_wn[e] = wn;
    }

    #pragma unroll
    for (int j = 0; j < 16; j++) {
        int src = j * 2 + half;
        float wnj = __shfl_sync(0xffffffffu, wn, src);
        int   cj  = __shfl_sync(0xffffffffu, c, src);
        int   rj  = __shfl_sync(0xffffffffu, r, src);
        if (wnj != 0.f && (ebase + src) < n_edges) {
            float4 v = ((const float4*)(x + (size_t)cj * D))[sub];
            v.x *= wnj; v.y *= wnj; v.z *= wnj; v.w *= wnj;
            float* dst = g_agg + (size_t)rj * D + sub * 4;
            asm volatile("red.global.add.v4.f32 [%0], {%1,%2,%3,%4};"
                         :: "l"(dst), "f"(v.x), "f"(v.y), "f"(v.z), "f"(v.w)
                         : "memory");
        }
    }
}

// ---- FFMA2 helpers (packed f32x2, sm_103a) ----
__device__ __forceinline__ unsigned long long dup2(float v) {
    unsigned long long r;
    asm("mov.b64 %0, {%1, %1};" : "=l"(r) : "r"(__float_as_uint(v)));
    return r;
}
__device__ __forceinline__ void ffma2(unsigned long long& acc,
                                      unsigned long long a, unsigned long long b) {
    asm("fma.rn.f32x2 %0, %1, %2, %0;" : "+l"(acc) : "l"(a), "l"(b));
}
__device__ __forceinline__ void unpack2(unsigned long long v, float& lo, float& hi) {
    unsigned l, h;
    asm("mov.b64 {%0, %1}, %2;" : "=r"(l), "=r"(h) : "l"(v));
    lo = __uint_as_float(l); hi = __uint_as_float(h);
}

// ---- 6: fused dual GEMM (FFMA2): out = (rho*x)@Ws^T + agg@Wn^T + tau*x ----
#define TILE_N 128
__global__ __launch_bounds__(128, 2) void k_gemm(const float* __restrict__ x,
                                                 const float* __restrict__ Ws,
                                                 const float* __restrict__ Wn,
                                                 float* __restrict__ out,
                                                 int n_nodes) {
    extern __shared__ float smem[];
    float* sxT = smem;                 // [64][128]  rho*x transposed
    float* saT = sxT + D * TILE_N;     // [64][128]  agg transposed
    float* swT = saT + D * TILE_N;     // [64][64]   Ws[k][d]
    float* snT = swT + D * D;          // [64][64]   Wn[k][d]

    int t = threadIdx.x;
    int nbase = blockIdx.x * TILE_N;

    for (int i = t; i < D * D; i += 128) {
        int k = i >> 6, d = i & 63;
        swT[k * D + d] = Ws[d * D + k];
        snT[k * D + d] = Wn[d * D + k];
    }
    for (int i = t; i < TILE_N * (D / 4); i += 128) {
        int n  = i & (TILE_N - 1);
        int k4 = i >> 7;                 // 0..15
        int gn = nbase + n;
        float4 xv = make_float4(0.f, 0.f, 0.f, 0.f);
        float4 av = make_float4(0.f, 0.f, 0.f, 0.f);
        float rho = 0.f;
        if (gn < n_nodes) {
            xv  = *(const float4*)(x     + (size_t)gn * D + k4 * 4);
            av  = *(const float4*)(g_agg + (size_t)gn * D + k4 * 4);
            rho = g_rho[gn];
        }
        sxT[(k4 * 4 + 0) * TILE_N + n] = rho * xv.x;
        sxT[(k4 * 4 + 1) * TILE_N + n] = rho * xv.y;
        sxT[(k4 * 4 + 2) * TILE_N + n] = rho * xv.z;
        sxT[(k4 * 4 + 3) * TILE_N + n] = rho * xv.w;
        saT[(k4 * 4 + 0) * TILE_N + n] = av.x;
        saT[(k4 * 4 + 1) * TILE_N + n] = av.y;
        saT[(k4 * 4 + 2) * TILE_N + n] = av.z;
        saT[(k4 * 4 + 3) * TILE_N + n] = av.w;
    }
    __syncthreads();

    int ng = t >> 3;   // 0..15 -> nodes ng*8 .. +7
    int dg = t & 7;    // 0..7  -> dims  dg*8 .. +7 (4 packed pairs)

    unsigned long long acc[8][4];
    #pragma unroll
    for (int i = 0; i < 8; i++)
        #pragma unroll
        for (int j = 0; j < 4; j++) acc[i][j] = 0ull;

    #pragma unroll 2
    for (int k = 0; k < D; k++) {
        float4 a0 = *(float4*)&sxT[k * TILE_N + ng * 8];
        float4 a1 = *(float4*)&sxT[k * TILE_N + ng * 8 + 4];
        float4 g0 = *(float4*)&saT[k * TILE_N + ng * 8];
        float4 g1 = *(float4*)&saT[k * TILE_N + ng * 8 + 4];
        ulonglong2 b0 = *(ulonglong2*)&swT[k * D + dg * 8];
        ulonglong2 b1 = *(ulonglong2*)&swT[k * D + dg * 8 + 4];
        ulonglong2 c0 = *(ulonglong2*)&snT[k * D + dg * 8];
        ulonglong2 c1 = *(ulonglong2*)&snT[k * D + dg * 8 + 4];
        unsigned long long bv[4] = {b0.x, b0.y, b1.x, b1.y};
        unsigned long long cv[4] = {c0.x, c0.y, c1.x, c1.y};
        float av[8] = {a0.x, a0.y, a0.z, a0.w, a1.x, a1.y, a1.z, a1.w};
        float gv[8] = {g0.x, g0.y, g0.z, g0.w, g1.x, g1.y, g1.z, g1.w};
        #pragma unroll
        for (int i = 0; i < 8; i++) {
            unsigned long long ad = dup2(av[i]);
            unsigned long long gd = dup2(gv[i]);
            #pragma unroll
            for (int j = 0; j < 4; j++) {
                ffma2(acc[i][j], ad, bv[j]);
                ffma2(acc[i][j], gd, cv[j]);
            }
        }
    }

    #pragma unroll
    for (int i = 0; i < 8; i++) {
        int gn = nbase + ng * 8 + i;
        if (gn >= n_nodes) continue;
        const float* xr = x + (size_t)gn * D + dg * 8;
        float* orow = out + (size_t)gn * D + dg * 8;
        float4 x0 = *(const float4*)(xr);
        float4 x1 = *(const float4*)(xr + 4);
        float r0, r1, r2, r3, r4, r5, r6, r7;
        unpack2(acc[i][0], r0, r1);
        unpack2(acc[i][1], r2, r3);
        unpack2(acc[i][2], r4, r5);
        unpack2(acc[i][3], r6, r7);
        float4 o0 = make_float4(r0 + TAUF * x0.x, r1 + TAUF * x0.y,
                                r2 + TAUF * x0.z, r3 + TAUF * x0.w);
        float4 o1 = make_float4(r4 + TAUF * x1.x, r5 + TAUF * x1.y,
                                r6 + TAUF * x1.z, r7 + TAUF * x1.w);
        *(float4*)(orow)     = o0;
        *(float4*)(orow + 4) = o1;
    }
}

extern "C" void kernel_launch(void* const* d_in, const int* in_sizes, int n_in,
                              void* d_out, int out_size) {
    const float* x  = (const float*)d_in[0];
    const void*  ei = d_in[1];
    const float* w  = (const float*)d_in[2];
    const float* Ws = (const float*)d_in[3];
    const float* Wn = (const float*)d_in[4];

    int n_nodes = in_sizes[0] / D;
    int n_edges = in_sizes[1] / 2;

    float* out_main = (float*)d_out;
    float* out_ei = nullptr;
    float* out_wn = nullptr;
    long long need_full = (long long)n_nodes * D + 3LL * n_edges;
    bool full = ((long long)out_size >= need_full);
    if (full) {
        out_ei = out_main + (size_t)n_nodes * D;
        out_wn = out_ei + (size_t)2 * n_edges;
    }

    const int T = 256;
    int tot = n_nodes * D;

    k_init<<<(tot + T - 1) / T, T>>>((const int*)ei, n_nodes);
    k_cvtdeg<<<(n_edges + T - 1) / T, T>>>(ei, w, out_ei, n_edges);
    k_kappa<<<(n_edges + T - 1) / T, T>>>(n_edges);
    k_whalf<<<(n_edges + T - 1) / T, T>>>(w, n_edges);
    k_node<<<(n_nodes + T - 1) / T, T>>>(n_nodes);

    // one warp per 32 edges
    int n_warps = (n_edges + 31) / 32;
    int sc_blocks = (n_warps * 32 + T - 1) / T;
    k_scatter<<<sc_blocks, T>>>(x, out_wn, n_edges);

    int smem_bytes = (D * TILE_N * 2 + D * D * 2) * (int)sizeof(float); // 96KB
    cudaFuncSetAttribute(k_gemm, cudaFuncAttributeMaxDynamicSharedMemorySize, smem_bytes);
    int gblocks = (n_nodes + TILE_N - 1) / TILE_N;
    k_gemm<<<gblocks, 128, smem_bytes>>>(x, Ws, Wn, out_main, n_nodes);
}

// round 6
// speedup vs baseline: 1.4063x; 1.0597x over previous
#include <cuda_runtime.h>
#include <cstdint>
#include <math.h>

#define MAXN 100000
#define MAXE 1600000
#define D 64
#define EPSF 1e-12f
#define SEPS 1e-6f
#define TAUF 0.5f

// ---- scratch (device globals: no allocation allowed) ----
__device__ float    g_deg[MAXN];
__device__ __align__(16) float4 g_nodeacc[MAXN];  // {rowsum, cnt, ksum, pad}
__device__ float    g_rho[MAXN];
__device__ float    g_irs[MAXN];       // 1 / max(rowsum, eps)
__device__ int      g_row[MAXE];
__device__ int      g_col[MAXE];
__device__ float    g_kappa[MAXE];
__device__ float    g_whalf[MAXE];
__device__ __align__(16) float g_agg[MAXN * D];   // sum_e w_norm * x[col]
__device__ unsigned g_maxbits;
__device__ int      g_is64;

__device__ __forceinline__ int get_idx(const void* ei, long long pos) {
    if (g_is64) return (int)((const long long*)ei)[pos];
    return ((const int*)ei)[pos];
}

// ---- 0: zero scratch + dtype detect (block 0) ----
__global__ void k_init(const int* __restrict__ eib, int n_nodes) {
    if (blockIdx.x == 0) {
        __shared__ int any;
        if (threadIdx.x == 0) any = 0;
        __syncthreads();
        int acc = 0;
        for (int j = threadIdx.x; j < 2048; j += blockDim.x)
            acc |= eib[2 * j + 1];           // high words of first 2048 int64s
        if (acc != 0) atomicOr(&any, 1);
        __syncthreads();
        if (threadIdx.x == 0) {
            g_is64 = (any == 0) ? 1 : 0;
            g_maxbits = 0u;
        }
    }
    int i = blockIdx.x * blockDim.x + threadIdx.x;
    int tot = n_nodes * D;
    if (i < tot) g_agg[i] = 0.f;
    if (i < n_nodes) {
        g_deg[i] = 0.f;
        g_nodeacc[i] = make_float4(0.f, 0.f, 0.f, 0.f);
    }
}

// ---- 1: convert indices to int32 + write edge_index output + weighted degree ----
__global__ void k_cvtdeg(const void* __restrict__ ei, const float* __restrict__ w,
                         float* __restrict__ out_ei, int n_edges) {
    int e = blockIdx.x * blockDim.x + threadIdx.x;
    if (e >= n_edges) return;
    int r = get_idx(ei, e);
    int c = get_idx(ei, (long long)n_edges + e);
    g_row[e] = r;
    g_col[e] = c;
    if (out_ei) {
        out_ei[e] = (float)r;
        out_ei[n_edges + e] = (float)c;
    }
    atomicAdd(&g_deg[r], w[e]);
}

// ---- 2: kappa per edge (invd2 inline) + global max|kappa| ----
__global__ void k_kappa(int n_edges) {
    int e = blockIdx.x * blockDim.x + threadIdx.x;
    float m = 0.f;
    if (e < n_edges) {
        float idu = 2.f / fmaxf(g_deg[g_row[e]], EPSF);
        float idv = 2.f / fmaxf(g_deg[g_col[e]], EPSF);
        float kap = idu + idv - 2.f;
        g_kappa[e] = kap;
        m = fabsf(kap);
    }
    #pragma unroll
    for (int o = 16; o > 0; o >>= 1)
        m = fmaxf(m, __shfl_xor_sync(0xffffffffu, m, o));
    if ((threadIdx.x & 31) == 0)
        atomicMax(&g_maxbits, __float_as_uint(m));   // m >= 0: uint order == float order
}

// ---- 3: half-step (dt inline) + surgery mask + single v4 node reduction ----
__global__ void k_whalf(const float* __restrict__ w, int n_edges) {
    int e = blockIdx.x * blockDim.x + threadIdx.x;
    if (e >= n_edges) return;
    float dt = 0.5f / (__uint_as_float(g_maxbits) + 1e-6f);
    float kap = g_kappa[e];
    float wh = fmaxf(w[e] * (1.f - 0.5f * dt * kap), 0.f);
    bool mask = wh > SEPS;
    if (!mask) wh = 0.f;
    g_whalf[e] = wh;
    int r = g_row[e];
    float cntv = mask ? 1.f : 0.f;
    float kv   = mask ? kap : 0.f;
    float* dst = (float*)&g_nodeacc[r];
    asm volatile("red.global.add.v4.f32 [%0], {%1,%2,%3,%4};"
                 :: "l"(dst), "f"(wh), "f"(cntv), "f"(kv), "f"(0.f)
                 : "memory");
}

// ---- 4: per-node inverse rowsum + curvature gate ----
__global__ void k_node(int n_nodes) {
    int n = blockIdx.x * blockDim.x + threadIdx.x;
    if (n >= n_nodes) return;
    float4 a = g_nodeacc[n];           // {rowsum, cnt, ksum, _}
    g_irs[n] = 1.f / fmaxf(a.x, EPSF);
    float mk = a.z / fmaxf(a.y, 1.f);
    g_rho[n] = 1.f / (1.f + expf(-mk));
}

// ---- 5: x-space scatter, warp-cooperative ----
__global__ void k_scatter(const float* __restrict__ x,
                          float* __restrict__ out_wn, int n_edges) {
    int warp_g = (blockIdx.x * blockDim.x + threadIdx.x) >> 5;
    int lane = threadIdx.x & 31;
    int sub  = lane & 15;
    int half = lane >> 4;
    int ebase = warp_g * 32;
    if (ebase >= n_edges) return;
    int e = ebase + lane;

    int r = 0, c = 0;
    float wn = 0.f;
    if (e < n_edges) {
        r = g_row[e];
        c = g_col[e];
        wn = g_whalf[e] * g_irs[r];
        if (out_wn) out_wn[e] = wn;
    }

    #pragma unroll
    for (int j = 0; j < 16; j++) {
        int src = j * 2 + half;
        float wnj = __shfl_sync(0xffffffffu, wn, src);
        int   cj  = __shfl_sync(0xffffffffu, c, src);
        int   rj  = __shfl_sync(0xffffffffu, r, src);
        if (wnj != 0.f && (ebase + src) < n_edges) {
            float4 v = ((const float4*)(x + (size_t)cj * D))[sub];
            v.x *= wnj; v.y *= wnj; v.z *= wnj; v.w *= wnj;
            float* dst = g_agg + (size_t)rj * D + sub * 4;
            asm volatile("red.global.add.v4.f32 [%0], {%1,%2,%3,%4};"
                         :: "l"(dst), "f"(v.x), "f"(v.y), "f"(v.z), "f"(v.w)
                         : "memory");
        }
    }
}

// ---- FFMA2 helpers (packed f32x2, sm_103a) ----
__device__ __forceinline__ unsigned long long dup2(float v) {
    unsigned long long r;
    asm("mov.b64 %0, {%1, %1};" : "=l"(r) : "r"(__float_as_uint(v)));
    return r;
}
__device__ __forceinline__ void ffma2(unsigned long long& acc,
                                      unsigned long long a, unsigned long long b) {
    asm("fma.rn.f32x2 %0, %1, %2, %0;" : "+l"(acc) : "l"(a), "l"(b));
}
__device__ __forceinline__ void unpack2(unsigned long long v, float& lo, float& hi) {
    unsigned l, h;
    asm("mov.b64 {%0, %1}, %2;" : "=r"(l), "=r"(h) : "l"(v));
    lo = __uint_as_float(l); hi = __uint_as_float(h);
}

// ---- 6: fused dual GEMM (FFMA2): out = (rho*x)@Ws^T + agg@Wn^T + tau*x ----
#define TILE_N 128
__global__ __launch_bounds__(128, 2) void k_gemm(const float* __restrict__ x,
                                                 const float* __restrict__ Ws,
                                                 const float* __restrict__ Wn,
                                                 float* __restrict__ out,
                                                 int n_nodes) {
    extern __shared__ float smem[];
    float* sxT = smem;                 // [64][128]  rho*x transposed
    float* saT = sxT + D * TILE_N;     // [64][128]  agg transposed
    float* swT = saT + D * TILE_N;     // [64][64]   Ws[k][d]
    float* snT = swT + D * D;          // [64][64]   Wn[k][d]

    int t = threadIdx.x;
    int nbase = blockIdx.x * TILE_N;

    for (int i = t; i < D * D; i += 128) {
        int k = i >> 6, d = i & 63;
        swT[k * D + d] = Ws[d * D + k];
        snT[k * D + d] = Wn[d * D + k];
    }
    for (int i = t; i < TILE_N * (D / 4); i += 128) {
        int n  = i & (TILE_N - 1);
        int k4 = i >> 7;                 // 0..15
        int gn = nbase + n;
        float4 xv = make_float4(0.f, 0.f, 0.f, 0.f);
        float4 av = make_float4(0.f, 0.f, 0.f, 0.f);
        float rho = 0.f;
        if (gn < n_nodes) {
            xv  = *(const float4*)(x     + (size_t)gn * D + k4 * 4);
            av  = *(const float4*)(g_agg + (size_t)gn * D + k4 * 4);
            rho = g_rho[gn];
        }
        sxT[(k4 * 4 + 0) * TILE_N + n] = rho * xv.x;
        sxT[(k4 * 4 + 1) * TILE_N + n] = rho * xv.y;
        sxT[(k4 * 4 + 2) * TILE_N + n] = rho * xv.z;
        sxT[(k4 * 4 + 3) * TILE_N + n] = rho * xv.w;
        saT[(k4 * 4 + 0) * TILE_N + n] = av.x;
        saT[(k4 * 4 + 1) * TILE_N + n] = av.y;
        saT[(k4 * 4 + 2) * TILE_N + n] = av.z;
        saT[(k4 * 4 + 3) * TILE_N + n] = av.w;
    }
    __syncthreads();

    int ng = t >> 3;   // 0..15 -> nodes ng*8 .. +7
    int dg = t & 7;    // 0..7  -> dims  dg*8 .. +7 (4 packed pairs)

    unsigned long long acc[8][4];
    #pragma unroll
    for (int i = 0; i < 8; i++)
        #pragma unroll
        for (int j = 0; j < 4; j++) acc[i][j] = 0ull;

    #pragma unroll 2
    for (int k = 0; k < D; k++) {
        float4 a0 = *(float4*)&sxT[k * TILE_N + ng * 8];
        float4 a1 = *(float4*)&sxT[k * TILE_N + ng * 8 + 4];
        float4 g0 = *(float4*)&saT[k * TILE_N + ng * 8];
        float4 g1 = *(float4*)&saT[k * TILE_N + ng * 8 + 4];
        ulonglong2 b0 = *(ulonglong2*)&swT[k * D + dg * 8];
        ulonglong2 b1 = *(ulonglong2*)&swT[k * D + dg * 8 + 4];
        ulonglong2 c0 = *(ulonglong2*)&snT[k * D + dg * 8];
        ulonglong2 c1 = *(ulonglong2*)&snT[k * D + dg * 8 + 4];
        unsigned long long bv[4] = {b0.x, b0.y, b1.x, b1.y};
        unsigned long long cv[4] = {c0.x, c0.y, c1.x, c1.y};
        float av[8] = {a0.x, a0.y, a0.z, a0.w, a1.x, a1.y, a1.z, a1.w};
        float gv[8] = {g0.x, g0.y, g0.z, g0.w, g1.x, g1.y, g1.z, g1.w};
        #pragma unroll
        for (int i = 0; i < 8; i++) {
            unsigned long long ad = dup2(av[i]);
            unsigned long long gd = dup2(gv[i]);
            #pragma unroll
            for (int j = 0; j < 4; j++) {
                ffma2(acc[i][j], ad, bv[j]);
                ffma2(acc[i][j], gd, cv[j]);
            }
        }
    }

    #pragma unroll
    for (int i = 0; i < 8; i++) {
        int gn = nbase + ng * 8 + i;
        if (gn >= n_nodes) continue;
        const float* xr = x + (size_t)gn * D + dg * 8;
        float* orow = out + (size_t)gn * D + dg * 8;
        float4 x0 = *(const float4*)(xr);
        float4 x1 = *(const float4*)(xr + 4);
        float r0, r1, r2, r3, r4, r5, r6, r7;
        unpack2(acc[i][0], r0, r1);
        unpack2(acc[i][1], r2, r3);
        unpack2(acc[i][2], r4, r5);
        unpack2(acc[i][3], r6, r7);
        float4 o0 = make_float4(r0 + TAUF * x0.x, r1 + TAUF * x0.y,
                                r2 + TAUF * x0.z, r3 + TAUF * x0.w);
        float4 o1 = make_float4(r4 + TAUF * x1.x, r5 + TAUF * x1.y,
                                r6 + TAUF * x1.z, r7 + TAUF * x1.w);
        *(float4*)(orow)     = o0;
        *(float4*)(orow + 4) = o1;
    }
}

extern "C" void kernel_launch(void* const* d_in, const int* in_sizes, int n_in,
                              void* d_out, int out_size) {
    const float* x  = (const float*)d_in[0];
    const void*  ei = d_in[1];
    const float* w  = (const float*)d_in[2];
    const float* Ws = (const float*)d_in[3];
    const float* Wn = (const float*)d_in[4];

    int n_nodes = in_sizes[0] / D;
    int n_edges = in_sizes[1] / 2;

    float* out_main = (float*)d_out;
    float* out_ei = nullptr;
    float* out_wn = nullptr;
    long long need_full = (long long)n_nodes * D + 3LL * n_edges;
    bool full = ((long long)out_size >= need_full);
    if (full) {
        out_ei = out_main + (size_t)n_nodes * D;
        out_wn = out_ei + (size_t)2 * n_edges;
    }

    const int T = 256;
    int tot = n_nodes * D;

    k_init<<<(tot + T - 1) / T, T>>>((const int*)ei, n_nodes);
    k_cvtdeg<<<(n_edges + T - 1) / T, T>>>(ei, w, out_ei, n_edges);
    k_kappa<<<(n_edges + T - 1) / T, T>>>(n_edges);
    k_whalf<<<(n_edges + T - 1) / T, T>>>(w, n_edges);
    k_node<<<(n_nodes + T - 1) / T, T>>>(n_nodes);

    int n_warps = (n_edges + 31) / 32;
    int sc_blocks = (n_warps * 32 + T - 1) / T;
    k_scatter<<<sc_blocks, T>>>(x, out_wn, n_edges);

    int smem_bytes = (D * TILE_N * 2 + D * D * 2) * (int)sizeof(float); // 96KB
    cudaFuncSetAttribute(k_gemm, cudaFuncAttributeMaxDynamicSharedMemorySize, smem_bytes);
    int gblocks = (n_nodes + TILE_N - 1) / TILE_N;
    k_gemm<<<gblocks, 128, smem_bytes>>>(x, Ws, Wn, out_main, n_nodes);
}

// round 7
// speedup vs baseline: 1.4638x; 1.0409x over previous
#include <cuda_runtime.h>
#include <cstdint>
#include <math.h>

#define MAXN 100000
#define MAXE 1600000
#define D 64
#define EPSF 1e-12f
#define SEPS 1e-6f
#define TAUF 0.5f

// ---- scratch (device globals: no allocation allowed) ----
__device__ float    g_deg[MAXN];
__device__ __align__(16) float4 g_nodeacc[MAXN];  // {rowsum, cnt, ksum, pad}
__device__ float    g_rho[MAXN];
__device__ float    g_irs[MAXN];
__device__ int      g_hist[MAXN];      // all-edge row histogram
__device__ int      g_startl[MAXN];    // in-block exclusive scan
__device__ int      g_start[MAXN];     // CSR row start
__device__ int      g_cursor[MAXN];    // fill cursor / final end
__device__ int      g_bsum[512];
__device__ int      g_boff[512];
__device__ int      g_row[MAXE];
__device__ int      g_col[MAXE];
__device__ float    g_kappa[MAXE];
__device__ float    g_whalf[MAXE];
__device__ int      g_scol[MAXE];      // CSR-sorted col
__device__ float    g_swn[MAXE];       // CSR-sorted w_norm
__device__ __align__(16) float g_agg[MAXN * D];
__device__ unsigned g_maxbits;
__device__ int      g_is64;

__device__ __forceinline__ int get_idx(const void* ei, long long pos) {
    if (g_is64) return (int)((const long long*)ei)[pos];
    return ((const int*)ei)[pos];
}

// ---- 0: zero node scratch + dtype detect (block 0) ----
__global__ void k_init(const int* __restrict__ eib, int n_nodes) {
    if (blockIdx.x == 0) {
        __shared__ int any;
        if (threadIdx.x == 0) any = 0;
        __syncthreads();
        int acc = 0;
        for (int j = threadIdx.x; j < 2048; j += blockDim.x)
            acc |= eib[2 * j + 1];
        if (acc != 0) atomicOr(&any, 1);
        __syncthreads();
        if (threadIdx.x == 0) {
            g_is64 = (any == 0) ? 1 : 0;
            g_maxbits = 0u;
        }
    }
    int i = blockIdx.x * blockDim.x + threadIdx.x;
    if (i < n_nodes) {
        g_deg[i] = 0.f;
        g_hist[i] = 0;
        g_nodeacc[i] = make_float4(0.f, 0.f, 0.f, 0.f);
    }
}

// ---- 1: convert + edge_index output + degree + row histogram ----
__global__ void k_cvtdeg(const void* __restrict__ ei, const float* __restrict__ w,
                         float* __restrict__ out_ei, int n_edges) {
    int e = blockIdx.x * blockDim.x + threadIdx.x;
    if (e >= n_edges) return;
    int r = get_idx(ei, e);
    int c = get_idx(ei, (long long)n_edges + e);
    g_row[e] = r;
    g_col[e] = c;
    if (out_ei) {
        out_ei[e] = (float)r;
        out_ei[n_edges + e] = (float)c;
    }
    atomicAdd(&g_deg[r], w[e]);
    atomicAdd(&g_hist[r], 1);
}

// ---- 2: kappa per edge + global max|kappa| ----
__global__ void k_kappa(int n_edges) {
    int e = blockIdx.x * blockDim.x + threadIdx.x;
    float m = 0.f;
    if (e < n_edges) {
        float idu = 2.f / fmaxf(g_deg[g_row[e]], EPSF);
        float idv = 2.f / fmaxf(g_deg[g_col[e]], EPSF);
        float kap = idu + idv - 2.f;
        g_kappa[e] = kap;
        m = fabsf(kap);
    }
    #pragma unroll
    for (int o = 16; o > 0; o >>= 1)
        m = fmaxf(m, __shfl_xor_sync(0xffffffffu, m, o));
    if ((threadIdx.x & 31) == 0)
        atomicMax(&g_maxbits, __float_as_uint(m));
}

// ---- 3: half-step + surgery mask + single v4 node reduction ----
__global__ void k_whalf(const float* __restrict__ w, int n_edges) {
    int e = blockIdx.x * blockDim.x + threadIdx.x;
    if (e >= n_edges) return;
    float dt = 0.5f / (__uint_as_float(g_maxbits) + 1e-6f);
    float kap = g_kappa[e];
    float wh = fmaxf(w[e] * (1.f - 0.5f * dt * kap), 0.f);
    bool mask = wh > SEPS;
    if (!mask) wh = 0.f;
    g_whalf[e] = wh;
    int r = g_row[e];
    float cntv = mask ? 1.f : 0.f;
    float kv   = mask ? kap : 0.f;
    float* dst = (float*)&g_nodeacc[r];
    asm volatile("red.global.add.v4.f32 [%0], {%1,%2,%3,%4};"
                 :: "l"(dst), "f"(wh), "f"(cntv), "f"(kv), "f"(0.f)
                 : "memory");
}

// ---- 4a: per-block scan of histogram ----
__global__ void k_scan1(int n_nodes) {
    __shared__ int sh[256];
    int n = blockIdx.x * 256 + threadIdx.x;
    int v = (n < n_nodes) ? g_hist[n] : 0;
    sh[threadIdx.x] = v;
    __syncthreads();
    #pragma unroll
    for (int o = 1; o < 256; o <<= 1) {
        int t = (threadIdx.x >= o) ? sh[threadIdx.x - o] : 0;
        __syncthreads();
        sh[threadIdx.x] += t;
        __syncthreads();
    }
    int incl = sh[threadIdx.x];
    if (n < n_nodes) g_startl[n] = incl - v;
    if (threadIdx.x == 255) g_bsum[blockIdx.x] = incl;
}

// ---- 4b: scan of block sums (nb <= 512) ----
__global__ void k_scan2(int nb) {
    __shared__ int sh[512];
    int v = (threadIdx.x < nb) ? g_bsum[threadIdx.x] : 0;
    sh[threadIdx.x] = v;
    __syncthreads();
    #pragma unroll
    for (int o = 1; o < 512; o <<= 1) {
        int t = (threadIdx.x >= o) ? sh[threadIdx.x - o] : 0;
        __syncthreads();
        sh[threadIdx.x] += t;
        __syncthreads();
    }
    if (threadIdx.x < nb) g_boff[threadIdx.x] = sh[threadIdx.x] - v;
}

// ---- 4c: finalize starts + per-node gate math ----
__global__ void k_scan3(int n_nodes) {
    int n = blockIdx.x * blockDim.x + threadIdx.x;
    if (n >= n_nodes) return;
    int s = g_startl[n] + g_boff[n >> 8];
    g_start[n] = s;
    g_cursor[n] = s;
    float4 a = g_nodeacc[n];
    g_irs[n] = 1.f / fmaxf(a.x, EPSF);
    float mk = a.z / fmaxf(a.y, 1.f);
    g_rho[n] = 1.f / (1.f + expf(-mk));
}

// ---- 5: reorder surviving edges into CSR slots; write w_norm output ----
__global__ void k_reorder(float* __restrict__ out_wn, int n_edges) {
    int e = blockIdx.x * blockDim.x + threadIdx.x;
    if (e >= n_edges) return;
    int r = g_row[e];
    float wn = g_whalf[e] * g_irs[r];
    if (out_wn) out_wn[e] = wn;
    if (wn != 0.f) {
        int pos = atomicAdd(&g_cursor[r], 1);
        g_scol[pos] = g_col[e];
        g_swn[pos] = wn;
    }
}

// ---- 6: CSR gather-accumulate, one warp per node, no atomics ----
__global__ void k_gather(const float* __restrict__ x, int n_nodes) {
    int warp = (blockIdx.x * blockDim.x + threadIdx.x) >> 5;
    if (warp >= n_nodes) return;
    int lane = threadIdx.x & 31;
    int sub  = lane & 15;
    int half = lane >> 4;
    int s = g_start[warp];
    int epos = g_cursor[warp];   // final fill position = row end

    float4 acc = make_float4(0.f, 0.f, 0.f, 0.f);
    for (int p = s + half; p < epos; p += 2) {
        int   c  = g_scol[p];
        float wn = g_swn[p];
        float4 v = ((const float4*)(x + (size_t)c * D))[sub];
        acc.x += wn * v.x; acc.y += wn * v.y;
        acc.z += wn * v.z; acc.w += wn * v.w;
    }
    acc.x += __shfl_xor_sync(0xffffffffu, acc.x, 16);
    acc.y += __shfl_xor_sync(0xffffffffu, acc.y, 16);
    acc.z += __shfl_xor_sync(0xffffffffu, acc.z, 16);
    acc.w += __shfl_xor_sync(0xffffffffu, acc.w, 16);
    if (half == 0)
        *(float4*)(g_agg + (size_t)warp * D + sub * 4) = acc;
}

// ---- FFMA2 helpers (packed f32x2, sm_103a) ----
__device__ __forceinline__ unsigned long long dup2(float v) {
    unsigned long long r;
    asm("mov.b64 %0, {%1, %1};" : "=l"(r) : "r"(__float_as_uint(v)));
    return r;
}
__device__ __forceinline__ void ffma2(unsigned long long& acc,
                                      unsigned long long a, unsigned long long b) {
    asm("fma.rn.f32x2 %0, %1, %2, %0;" : "+l"(acc) : "l"(a), "l"(b));
}
__device__ __forceinline__ void unpack2(unsigned long long v, float& lo, float& hi) {
    unsigned l, h;
    asm("mov.b64 {%0, %1}, %2;" : "=r"(l), "=r"(h) : "l"(v));
    lo = __uint_as_float(l); hi = __uint_as_float(h);
}

// ---- 7: fused dual GEMM (FFMA2): out = (rho*x)@Ws^T + agg@Wn^T + tau*x ----
#define TILE_N 128
__global__ __launch_bounds__(128, 2) void k_gemm(const float* __restrict__ x,
                                                 const float* __restrict__ Ws,
                                                 const float* __restrict__ Wn,
                                                 float* __restrict__ out,
                                                 int n_nodes) {
    extern __shared__ float smem[];
    float* sxT = smem;
    float* saT = sxT + D * TILE_N;
    float* swT = saT + D * TILE_N;
    float* snT = swT + D * D;

    int t = threadIdx.x;
    int nbase = blockIdx.x * TILE_N;

    for (int i = t; i < D * D; i += 128) {
        int k = i >> 6, d = i & 63;
        swT[k * D + d] = Ws[d * D + k];
        snT[k * D + d] = Wn[d * D + k];
    }
    for (int i = t; i < TILE_N * (D / 4); i += 128) {
        int n  = i & (TILE_N - 1);
        int k4 = i >> 7;
        int gn = nbase + n;
        float4 xv = make_float4(0.f, 0.f, 0.f, 0.f);
        float4 av = make_float4(0.f, 0.f, 0.f, 0.f);
        float rho = 0.f;
        if (gn < n_nodes) {
            xv  = *(const float4*)(x     + (size_t)gn * D + k4 * 4);
            av  = *(const float4*)(g_agg + (size_t)gn * D + k4 * 4);
            rho = g_rho[gn];
        }
        sxT[(k4 * 4 + 0) * TILE_N + n] = rho * xv.x;
        sxT[(k4 * 4 + 1) * TILE_N + n] = rho * xv.y;
        sxT[(k4 * 4 + 2) * TILE_N + n] = rho * xv.z;
        sxT[(k4 * 4 + 3) * TILE_N + n] = rho * xv.w;
        saT[(k4 * 4 + 0) * TILE_N + n] = av.x;
        saT[(k4 * 4 + 1) * TILE_N + n] = av.y;
        saT[(k4 * 4 + 2) * TILE_N + n] = av.z;
        saT[(k4 * 4 + 3) * TILE_N + n] = av.w;
    }
    __syncthreads();

    int ng = t >> 3;
    int dg = t & 7;

    unsigned long long acc[8][4];
    #pragma unroll
    for (int i = 0; i < 8; i++)
        #pragma unroll
        for (int j = 0; j < 4; j++) acc[i][j] = 0ull;

    #pragma unroll 2
    for (int k = 0; k < D; k++) {
        float4 a0 = *(float4*)&sxT[k * TILE_N + ng * 8];
        float4 a1 = *(float4*)&sxT[k * TILE_N + ng * 8 + 4];
        float4 g0 = *(float4*)&saT[k * TILE_N + ng * 8];
        float4 g1 = *(float4*)&saT[k * TILE_N + ng * 8 + 4];
        ulonglong2 b0 = *(ulonglong2*)&swT[k * D + dg * 8];
        ulonglong2 b1 = *(ulonglong2*)&swT[k * D + dg * 8 + 4];
        ulonglong2 c0 = *(ulonglong2*)&snT[k * D + dg * 8];
        ulonglong2 c1 = *(ulonglong2*)&snT[k * D + dg * 8 + 4];
        unsigned long long bv[4] = {b0.x, b0.y, b1.x, b1.y};
        unsigned long long cv[4] = {c0.x, c0.y, c1.x, c1.y};
        float av[8] = {a0.x, a0.y, a0.z, a0.w, a1.x, a1.y, a1.z, a1.w};
        float gv[8] = {g0.x, g0.y, g0.z, g0.w, g1.x, g1.y, g1.z, g1.w};
        #pragma unroll
        for (int i = 0; i < 8; i++) {
            unsigned long long ad = dup2(av[i]);
            unsigned long long gd = dup2(gv[i]);
            #pragma unroll
            for (int j = 0; j < 4; j++) {
                ffma2(acc[i][j], ad, bv[j]);
                ffma2(acc[i][j], gd, cv[j]);
            }
        }
    }

    #pragma unroll
    for (int i = 0; i < 8; i++) {
        int gn = nbase + ng * 8 + i;
        if (gn >= n_nodes) continue;
        const float* xr = x + (size_t)gn * D + dg * 8;
        float* orow = out + (size_t)gn * D + dg * 8;
        float4 x0 = *(const float4*)(xr);
        float4 x1 = *(const float4*)(xr + 4);
        float r0, r1, r2, r3, r4, r5, r6, r7;
        unpack2(acc[i][0], r0, r1);
        unpack2(acc[i][1], r2, r3);
        unpack2(acc[i][2], r4, r5);
        unpack2(acc[i][3], r6, r7);
        float4 o0 = make_float4(r0 + TAUF * x0.x, r1 + TAUF * x0.y,
                                r2 + TAUF * x0.z, r3 + TAUF * x0.w);
        float4 o1 = make_float4(r4 + TAUF * x1.x, r5 + TAUF * x1.y,
                                r6 + TAUF * x1.z, r7 + TAUF * x1.w);
        *(float4*)(orow)     = o0;
        *(float4*)(orow + 4) = o1;
    }
}

extern "C" void kernel_launch(void* const* d_in, const int* in_sizes, int n_in,
                              void* d_out, int out_size) {
    const float* x  = (const float*)d_in[0];
    const void*  ei = d_in[1];
    const float* w  = (const float*)d_in[2];
    const float* Ws = (const float*)d_in[3];
    const float* Wn = (const float*)d_in[4];

    int n_nodes = in_sizes[0] / D;
    int n_edges = in_sizes[1] / 2;

    float* out_main = (float*)d_out;
    float* out_ei = nullptr;
    float* out_wn = nullptr;
    long long need_full = (long long)n_nodes * D + 3LL * n_edges;
    bool full = ((long long)out_size >= need_full);
    if (full) {
        out_ei = out_main + (size_t)n_nodes * D;
        out_wn = out_ei + (size_t)2 * n_edges;
    }

    const int T = 256;
    int nblk = (n_nodes + T - 1) / T;

    k_init<<<nblk, T>>>((const int*)ei, n_nodes);
    k_cvtdeg<<<(n_edges + T - 1) / T, T>>>(ei, w, out_ei, n_edges);
    k_kappa<<<(n_edges + T - 1) / T, T>>>(n_edges);
    k_whalf<<<(n_edges + T - 1) / T, T>>>(w, n_edges);
    k_scan1<<<nblk, 256>>>(n_nodes);
    k_scan2<<<1, 512>>>(nblk);
    k_scan3<<<nblk, T>>>(n_nodes);
    k_reorder<<<(n_edges + T - 1) / T, T>>>(out_wn, n_edges);

    int gw_blocks = (n_nodes * 32 + T - 1) / T;
    k_gather<<<gw_blocks, T>>>(x, n_nodes);

    int smem_bytes = (D * TILE_N * 2 + D * D * 2) * (int)sizeof(float); // 96KB
    cudaFuncSetAttribute(k_gemm, cudaFuncAttributeMaxDynamicSharedMemorySize, smem_bytes);
    int gblocks = (n_nodes + TILE_N - 1) / TILE_N;
    k_gemm<<<gblocks, 128, smem_bytes>>>(x, Ws, Wn, out_main, n_nodes);
}

// round 8
// speedup vs baseline: 1.5898x; 1.0861x over previous
#include <cuda_runtime.h>
#include <cstdint>
#include <math.h>

#define MAXN 100000
#define MAXE 1600000
#define D 64
#define EPSF 1e-12f
#define SEPS 1e-6f
#define TAUF 0.5f

// ---- scratch (device globals: no allocation allowed) ----
__device__ __align__(8)  float2 g_deghist[MAXN];   // {weighted deg, edge count}
__device__ __align__(16) float4 g_nodeacc[MAXN];   // {rowsum, cnt, ksum, pad}
__device__ float    g_rho[MAXN];
__device__ float    g_irs[MAXN];
__device__ int      g_startl[MAXN];    // in-block exclusive scan
__device__ int      g_start[MAXN];     // CSR row start
__device__ int      g_cursor[MAXN];    // fill cursor / final end
__device__ int      g_bsum[512];
__device__ int      g_boff[512];
__device__ int      g_row[MAXE];
__device__ int      g_col[MAXE];
__device__ float    g_kappa[MAXE];
__device__ float    g_whalf[MAXE];
__device__ __align__(8) float2 g_scw[MAXE];  // CSR payload {bitcast col, w_norm}
__device__ __align__(16) float g_agg[MAXN * D];
__device__ unsigned g_maxbits;
__device__ int      g_is64;

__device__ __forceinline__ int get_idx(const void* ei, long long pos) {
    if (g_is64) return (int)((const long long*)ei)[pos];
    return ((const int*)ei)[pos];
}

// ---- 0: zero node scratch + dtype detect (block 0) ----
__global__ void k_init(const int* __restrict__ eib, int n_nodes) {
    if (blockIdx.x == 0) {
        __shared__ int any;
        if (threadIdx.x == 0) any = 0;
        __syncthreads();
        int acc = 0;
        for (int j = threadIdx.x; j < 2048; j += blockDim.x)
            acc |= eib[2 * j + 1];
        if (acc != 0) atomicOr(&any, 1);
        __syncthreads();
        if (threadIdx.x == 0) {
            g_is64 = (any == 0) ? 1 : 0;
            g_maxbits = 0u;
        }
    }
    int i = blockIdx.x * blockDim.x + threadIdx.x;
    if (i < n_nodes) {
        g_deghist[i] = make_float2(0.f, 0.f);
        g_nodeacc[i] = make_float4(0.f, 0.f, 0.f, 0.f);
    }
}

// ---- 1: convert + edge_index output + fused {deg,count} v2 reduction ----
__global__ void k_cvtdeg(const void* __restrict__ ei, const float* __restrict__ w,
                         float* __restrict__ out_ei, int n_edges) {
    int e = blockIdx.x * blockDim.x + threadIdx.x;
    if (e >= n_edges) return;
    int r = get_idx(ei, e);
    int c = get_idx(ei, (long long)n_edges + e);
    g_row[e] = r;
    g_col[e] = c;
    if (out_ei) {
        out_ei[e] = (float)r;
        out_ei[n_edges + e] = (float)c;
    }
    float* dst = (float*)&g_deghist[r];
    asm volatile("red.global.add.v2.f32 [%0], {%1,%2};"
                 :: "l"(dst), "f"(w[e]), "f"(1.0f) : "memory");
}

// ---- 2: kappa per edge + global max|kappa|; first nblk blocks also scan1 ----
__global__ void k_kappa(int n_edges, int n_nodes, int nblk) {
    __shared__ int sh[256];
    int t = threadIdx.x;

    // rider: per-block exclusive scan of histogram
    if ((int)blockIdx.x < nblk) {
        int n = blockIdx.x * 256 + t;
        int v = (n < n_nodes) ? (int)g_deghist[n].y : 0;
        sh[t] = v;
        __syncthreads();
        #pragma unroll
        for (int o = 1; o < 256; o <<= 1) {
            int u = (t >= o) ? sh[t - o] : 0;
            __syncthreads();
            sh[t] += u;
            __syncthreads();
        }
        int incl = sh[t];
        if (n < n_nodes) g_startl[n] = incl - v;
        if (t == 255) g_bsum[blockIdx.x] = incl;
    }

    int e = blockIdx.x * blockDim.x + t;
    float m = 0.f;
    if (e < n_edges) {
        float idu = 2.f / fmaxf(g_deghist[g_row[e]].x, EPSF);
        float idv = 2.f / fmaxf(g_deghist[g_col[e]].x, EPSF);
        float kap = idu + idv - 2.f;
        g_kappa[e] = kap;
        m = fabsf(kap);
    }
    #pragma unroll
    for (int o = 16; o > 0; o >>= 1)
        m = fmaxf(m, __shfl_xor_sync(0xffffffffu, m, o));
    if ((t & 31) == 0)
        atomicMax(&g_maxbits, __float_as_uint(m));
}

// ---- 3: half-step + surgery + v4 node reduction; block 0 also scan2 ----
__global__ void k_whalf(const float* __restrict__ w, int n_edges, int nb) {
    if (blockIdx.x == 0) {
        // double-buffered Hillis-Steele over up to 512 block sums, 256 threads
        __shared__ int sa[512], sb[512];
        int t = threadIdx.x;
        sa[t]       = (t < nb)       ? g_bsum[t]       : 0;
        sa[t + 256] = (t + 256 < nb) ? g_bsum[t + 256] : 0;
        __syncthreads();
        int* src = sa; int* dstb = sb;
        for (int o = 1; o < 512; o <<= 1) {
            int i0 = t, i1 = t + 256;
            dstb[i0] = src[i0] + ((i0 >= o) ? src[i0 - o] : 0);
            dstb[i1] = src[i1] + ((i1 >= o) ? src[i1 - o] : 0);
            __syncthreads();
            int* tmp = src; src = dstb; dstb = tmp;
        }
        // src holds inclusive scan
        if (t < nb)       g_boff[t]       = src[t]       - ((t < nb) ? ((t == 0) ? src[0] : src[t] - src[t-1]) : 0);
        // simpler: exclusive = inclusive - original
        __syncthreads();
        if (t < nb)       g_boff[t]       = src[t]       - g_bsum[t];
        if (t + 256 < nb) g_boff[t + 256] = src[t + 256] - g_bsum[t + 256];
    }

    int e = blockIdx.x * blockDim.x + threadIdx.x;
    if (e >= n_edges) return;
    float dt = 0.5f / (__uint_as_float(g_maxbits) + 1e-6f);
    float kap = g_kappa[e];
    float wh = fmaxf(w[e] * (1.f - 0.5f * dt * kap), 0.f);
    bool mask = wh > SEPS;
    if (!mask) wh = 0.f;
    g_whalf[e] = wh;
    int r = g_row[e];
    float cntv = mask ? 1.f : 0.f;
    float kv   = mask ? kap : 0.f;
    float* dst = (float*)&g_nodeacc[r];
    asm volatile("red.global.add.v4.f32 [%0], {%1,%2,%3,%4};"
                 :: "l"(dst), "f"(wh), "f"(cntv), "f"(kv), "f"(0.f)
                 : "memory");
}

// ---- 4: finalize CSR starts + per-node gate math ----
__global__ void k_scan3(int n_nodes) {
    int n = blockIdx.x * blockDim.x + threadIdx.x;
    if (n >= n_nodes) return;
    int s = g_startl[n] + g_boff[n >> 8];
    g_start[n] = s;
    g_cursor[n] = s;
    float4 a = g_nodeacc[n];
    g_irs[n] = 1.f / fmaxf(a.x, EPSF);
    float mk = a.z / fmaxf(a.y, 1.f);
    g_rho[n] = 1.f / (1.f + expf(-mk));
}

// ---- 5: reorder surviving edges into CSR slots; write w_norm output ----
__global__ void k_reorder(float* __restrict__ out_wn, int n_edges) {
    int e = blockIdx.x * blockDim.x + threadIdx.x;
    if (e >= n_edges) return;
    int r = g_row[e];
    float wn = g_whalf[e] * g_irs[r];
    if (out_wn) out_wn[e] = wn;
    if (wn != 0.f) {
        int pos = atomicAdd(&g_cursor[r], 1);
        g_scw[pos] = make_float2(__int_as_float(g_col[e]), wn);
    }
}

// ---- 6: CSR gather-accumulate, one warp per node, no atomics ----
__global__ void k_gather(const float* __restrict__ x, int n_nodes) {
    int warp = (blockIdx.x * blockDim.x + threadIdx.x) >> 5;
    if (warp >= n_nodes) return;
    int lane = threadIdx.x & 31;
    int sub  = lane & 15;
    int half = lane >> 4;
    int s = g_start[warp];
    int epos = g_cursor[warp];

    float4 acc = make_float4(0.f, 0.f, 0.f, 0.f);
    #pragma unroll 2
    for (int p = s + half; p < epos; p += 2) {
        float2 cw = g_scw[p];
        int   c  = __float_as_int(cw.x);
        float wn = cw.y;
        float4 v = ((const float4*)(x + (size_t)c * D))[sub];
        acc.x += wn * v.x; acc.y += wn * v.y;
        acc.z += wn * v.z; acc.w += wn * v.w;
    }
    acc.x += __shfl_xor_sync(0xffffffffu, acc.x, 16);
    acc.y += __shfl_xor_sync(0xffffffffu, acc.y, 16);
    acc.z += __shfl_xor_sync(0xffffffffu, acc.z, 16);
    acc.w += __shfl_xor_sync(0xffffffffu, acc.w, 16);
    if (half == 0)
        *(float4*)(g_agg + (size_t)warp * D + sub * 4) = acc;
}

// ---- FFMA2 helpers (packed f32x2, sm_103a) ----
__device__ __forceinline__ unsigned long long dup2(float v) {
    unsigned long long r;
    asm("mov.b64 %0, {%1, %1};" : "=l"(r) : "r"(__float_as_uint(v)));
    return r;
}
__device__ __forceinline__ void ffma2(unsigned long long& acc,
                                      unsigned long long a, unsigned long long b) {
    asm("fma.rn.f32x2 %0, %1, %2, %0;" : "+l"(acc) : "l"(a), "l"(b));
}
__device__ __forceinline__ void unpack2(unsigned long long v, float& lo, float& hi) {
    unsigned l, h;
    asm("mov.b64 {%0, %1}, %2;" : "=r"(l), "=r"(h) : "l"(v));
    lo = __uint_as_float(l); hi = __uint_as_float(h);
}

// ---- 7: fused dual GEMM (FFMA2): out = (rho*x)@Ws^T + agg@Wn^T + tau*x ----
#define TILE_N 128
__global__ __launch_bounds__(128, 2) void k_gemm(const float* __restrict__ x,
                                                 const float* __restrict__ Ws,
                                                 const float* __restrict__ Wn,
                                                 float* __restrict__ out,
                                                 int n_nodes) {
    extern __shared__ float smem[];
    float* sxT = smem;
    float* saT = sxT + D * TILE_N;
    float* swT = saT + D * TILE_N;
    float* snT = swT + D * D;

    int t = threadIdx.x;
    int nbase = blockIdx.x * TILE_N;

    for (int i = t; i < D * D; i += 128) {
        int k = i >> 6, d = i & 63;
        swT[k * D + d] = Ws[d * D + k];
        snT[k * D + d] = Wn[d * D + k];
    }
    for (int i = t; i < TILE_N * (D / 4); i += 128) {
        int n  = i & (TILE_N - 1);
        int k4 = i >> 7;
        int gn = nbase + n;
        float4 xv = make_float4(0.f, 0.f, 0.f, 0.f);
        float4 av = make_float4(0.f, 0.f, 0.f, 0.f);
        float rho = 0.f;
        if (gn < n_nodes) {
            xv  = *(const float4*)(x     + (size_t)gn * D + k4 * 4);
            av  = *(const float4*)(g_agg + (size_t)gn * D + k4 * 4);
            rho = g_rho[gn];
        }
        sxT[(k4 * 4 + 0) * TILE_N + n] = rho * xv.x;
        sxT[(k4 * 4 + 1) * TILE_N + n] = rho * xv.y;
        sxT[(k4 * 4 + 2) * TILE_N + n] = rho * xv.z;
        sxT[(k4 * 4 + 3) * TILE_N + n] = rho * xv.w;
        saT[(k4 * 4 + 0) * TILE_N + n] = av.x;
        saT[(k4 * 4 + 1) * TILE_N + n] = av.y;
        saT[(k4 * 4 + 2) * TILE_N + n] = av.z;
        saT[(k4 * 4 + 3) * TILE_N + n] = av.w;
    }
    __syncthreads();

    int ng = t >> 3;
    int dg = t & 7;

    unsigned long long acc[8][4];
    #pragma unroll
    for (int i = 0; i < 8; i++)
        #pragma unroll
        for (int j = 0; j < 4; j++) acc[i][j] = 0ull;

    #pragma unroll 2
    for (int k = 0; k < D; k++) {
        float4 a0 = *(float4*)&sxT[k * TILE_N + ng * 8];
        float4 a1 = *(float4*)&sxT[k * TILE_N + ng * 8 + 4];
        float4 g0 = *(float4*)&saT[k * TILE_N + ng * 8];
        float4 g1 = *(float4*)&saT[k * TILE_N + ng * 8 + 4];
        ulonglong2 b0 = *(ulonglong2*)&swT[k * D + dg * 8];
        ulonglong2 b1 = *(ulonglong2*)&swT[k * D + dg * 8 + 4];
        ulonglong2 c0 = *(ulonglong2*)&snT[k * D + dg * 8];
        ulonglong2 c1 = *(ulonglong2*)&snT[k * D + dg * 8 + 4];
        unsigned long long bv[4] = {b0.x, b0.y, b1.x, b1.y};
        unsigned long long cv[4] = {c0.x, c0.y, c1.x, c1.y};
        float av[8] = {a0.x, a0.y, a0.z, a0.w, a1.x, a1.y, a1.z, a1.w};
        float gv[8] = {g0.x, g0.y, g0.z, g0.w, g1.x, g1.y, g1.z, g1.w};
        #pragma unroll
        for (int i = 0; i < 8; i++) {
            unsigned long long ad = dup2(av[i]);
            unsigned long long gd = dup2(gv[i]);
            #pragma unroll
            for (int j = 0; j < 4; j++) {
                ffma2(acc[i][j], ad, bv[j]);
                ffma2(acc[i][j], gd, cv[j]);
            }
        }
    }

    #pragma unroll
    for (int i = 0; i < 8; i++) {
        int gn = nbase + ng * 8 + i;
        if (gn >= n_nodes) continue;
        const float* xr = x + (size_t)gn * D + dg * 8;
        float* orow = out + (size_t)gn * D + dg * 8;
        float4 x0 = *(const float4*)(xr);
        float4 x1 = *(const float4*)(xr + 4);
        float r0, r1, r2, r3, r4, r5, r6, r7;
        unpack2(acc[i][0], r0, r1);
        unpack2(acc[i][1], r2, r3);
        unpack2(acc[i][2], r4, r5);
        unpack2(acc[i][3], r6, r7);
        float4 o0 = make_float4(r0 + TAUF * x0.x, r1 + TAUF * x0.y,
                                r2 + TAUF * x0.z, r3 + TAUF * x0.w);
        float4 o1 = make_float4(r4 + TAUF * x1.x, r5 + TAUF * x1.y,
                                r6 + TAUF * x1.z, r7 + TAUF * x1.w);
        *(float4*)(orow)     = o0;
        *(float4*)(orow + 4) = o1;
    }
}

extern "C" void kernel_launch(void* const* d_in, const int* in_sizes, int n_in,
                              void* d_out, int out_size) {
    const float* x  = (const float*)d_in[0];
    const void*  ei = d_in[1];
    const float* w  = (const float*)d_in[2];
    const float* Ws = (const float*)d_in[3];
    const float* Wn = (const float*)d_in[4];

    int n_nodes = in_sizes[0] / D;
    int n_edges = in_sizes[1] / 2;

    float* out_main = (float*)d_out;
    float* out_ei = nullptr;
    float* out_wn = nullptr;
    long long need_full = (long long)n_nodes * D + 3LL * n_edges;
    bool full = ((long long)out_size >= need_full);
    if (full) {
        out_ei = out_main + (size_t)n_nodes * D;
        out_wn = out_ei + (size_t)2 * n_edges;
    }

    const int T = 256;
    int nblk = (n_nodes + T - 1) / T;
    int eblk = (n_edges + T - 1) / T;

    k_init<<<nblk, T>>>((const int*)ei, n_nodes);
    k_cvtdeg<<<eblk, T>>>(ei, w, out_ei, n_edges);
    k_kappa<<<eblk, T>>>(n_edges, n_nodes, nblk);
    k_whalf<<<eblk, T>>>(w, n_edges, nblk);
    k_scan3<<<nblk, T>>>(n_nodes);
    k_reorder<<<eblk, T>>>(out_wn, n_edges);

    int gw_blocks = (n_nodes * 32 + T - 1) / T;
    k_gather<<<gw_blocks, T>>>(x, n_nodes);

    int smem_bytes = (D * TILE_N * 2 + D * D * 2) * (int)sizeof(float); // 96KB
    cudaFuncSetAttribute(k_gemm, cudaFuncAttributeMaxDynamicSharedMemorySize, smem_bytes);
    int gblocks = (n_nodes + TILE_N - 1) / TILE_N;
    k_gemm<<<gblocks, 128, smem_bytes>>>(x, Ws, Wn, out_main, n_nodes);
}